// round 16
// baseline (speedup 1.0000x reference)
#include <cuda_runtime.h>
#include <cstdint>

#define T_LEN 65536
#define H 108
#define G4 432          // 4*H gate rows
#define NGATE 864       // 432 rows x 2 half-row threads (27 warps)
#define NTHR 896        // + 1 scalar warp

// ---------------- device scratch (static: no allocation allowed) ----------------
__device__ float g_imp[2][T_LEN];   // per-direction imputations (forward time order)
__device__ float g_loss[2];
__device__ float g_part[256];

// ---------------- f32x2 packed-FMA helpers ----------------
__device__ __forceinline__ void fma2(unsigned long long &acc, unsigned long long a, unsigned long long b) {
    asm volatile("fma.rn.f32x2 %0, %1, %2, %0;" : "+l"(acc) : "l"(a), "l"(b));
}
__device__ __forceinline__ unsigned long long pk2(float a, float b) {
    unsigned long long r;
    asm("mov.b64 %0, {%1, %2};" : "=l"(r) : "f"(a), "f"(b));
    return r;
}
__device__ __forceinline__ float2 upk(unsigned long long v) {
    float2 r;
    asm("mov.b64 {%0, %1}, %2;" : "=f"(r.x), "=f"(r.y) : "l"(v));
    return r;
}

// HW tanh (MUFU.TANH)
__device__ __forceinline__ float tanh_fast(float x) {
    float y;
    asm("tanh.approx.f32 %0, %1;" : "=f"(y) : "f"(x));
    return y;
}
__device__ __forceinline__ float sigmoid_fast(float x) {
    return fmaf(tanh_fast(0.5f * x), 0.5f, 0.5f);
}

// ---------------- main recurrence: one block per direction ----------------
__global__ void __launch_bounds__(NTHR, 1) brits_kernel(
    const float* __restrict__ values,  const float* __restrict__ masks,
    const float* __restrict__ deltas_f, const float* __restrict__ deltas_b,
    const float* __restrict__ f_td_w,  const float* __restrict__ f_td_b,
    const float* __restrict__ f_reg_w, const float* __restrict__ f_reg_b,
    const float* __restrict__ f_W_ih,  const float* __restrict__ f_W_hh,
    const float* __restrict__ f_b_ih,  const float* __restrict__ f_b_hh,
    const float* __restrict__ b_td_w,  const float* __restrict__ b_td_b,
    const float* __restrict__ b_reg_w, const float* __restrict__ b_reg_b,
    const float* __restrict__ b_W_ih,  const float* __restrict__ b_W_hh,
    const float* __restrict__ b_b_ih,  const float* __restrict__ b_b_hh)
{
    const int dir = blockIdx.x;
    const float* td_w  = dir ? b_td_w  : f_td_w;
    const float* td_b  = dir ? b_td_b  : f_td_b;
    const float* reg_w = dir ? b_reg_w : f_reg_w;
    const float* reg_b = dir ? b_reg_b : f_reg_b;
    const float* W_ih  = dir ? b_W_ih  : f_W_ih;
    const float* W_hh  = dir ? b_W_hh  : f_W_hh;
    const float* b_ih  = dir ? b_b_ih  : f_b_ih;
    const float* b_hh  = dir ? b_b_hh  : f_b_hh;
    const float* deltas = dir ? deltas_b : deltas_f;

    __shared__ __align__(16) float s_hd[128];   // decayed hidden; [108..127] = 0 pad
    __shared__ float s_gates[G4];               // W_hh @ h_decayed per gate row
    __shared__ float s_scalar[2];               // {x_c, m} for current step
    __shared__ float s_par[12][H];              // input weights / fused biases, SoA
    __shared__ float s_c[H];                    // cell state (smem to spare regs)
    __shared__ float s_tdw[H], s_tdb[H];        // decay params (smem)

    const int tid  = threadIdx.x;
    const int lane = tid & 31;
    const int row  = tid >> 1;     // gate row (gate threads)
    const int half = tid & 1;      // K-half: 0 -> floats [0,56), 1 -> [56,112)

    // ---- one-time init: half-row of W_hh in registers, 28 x f32x2 ----
    unsigned long long w[28];
    if (tid < NGATE) {
        const float* rw = W_hh + row * H + half * 56;
        const int nreal = half ? 52 : 56;     // valid floats in this half
        #pragma unroll
        for (int i = 0; i < 28; i++) {
            float a = (2 * i     < nreal) ? rw[2 * i]     : 0.0f;
            float b = (2 * i + 1 < nreal) ? rw[2 * i + 1] : 0.0f;
            w[i] = pk2(a, b);
        }
    } else {
        #pragma unroll
        for (int i = 0; i < 28; i++) w[i] = 0ull;
    }

    // s_par[kind*4+q][j]: kind0=W_ih[:,0], kind1=W_ih[:,1], kind2=b_ih+b_hh; row r=q*H+j
    for (int k = tid; k < 12 * H; k += NTHR) {
        int j = k % H;
        int f = k / H;
        int q = f & 3;
        int kind = f >> 2;
        int r = q * H + j;
        float v;
        if (kind == 0)      v = W_ih[2 * r];
        else if (kind == 1) v = W_ih[2 * r + 1];
        else                v = b_ih[r] + b_hh[r];
        s_par[f][j] = v;
    }

    if (tid < H) {
        s_c[tid]   = 0.0f;
        s_tdw[tid] = td_w[tid];
        s_tdb[tid] = td_b[tid];
    }
    if (tid < 128) s_hd[tid] = 0.0f;

    float loss = 0.0f, lcomp = 0.0f;   // Kahan loss accumulator (scalar warp lane 0)
    __syncthreads();

    const uint32_t hd_base = (uint32_t)__cvta_generic_to_shared(s_hd) + (uint32_t)(half * 224);

    for (int t = 0; t < T_LEN; ++t) {
        const int idx = dir ? (T_LEN - 1 - t) : t;

        // prefetch next step's delta early (LDG hides behind the matvec)
        float dn = 0.0f;
        if (tid < H) {
            int tn = (t + 1 < T_LEN) ? (t + 1) : (T_LEN - 1);
            dn = deltas[tn];
        }

        if (tid < NGATE) {
            // ---- half-row matvec: depth-2 software-pipelined LDS.128 + fma2 ----
            unsigned long long p0a, p0b, p1a, p1b;
            asm volatile("ld.shared.v2.u64 {%0, %1}, [%2];"
                         : "=l"(p0a), "=l"(p0b) : "r"(hd_base));
            unsigned long long acc0 = 0ull, acc1 = 0ull;
            #pragma unroll
            for (int i = 0; i < 14; i++) {
                if (i + 1 < 14) {
                    if (i & 1) {
                        asm volatile("ld.shared.v2.u64 {%0, %1}, [%2];"
                                     : "=l"(p0a), "=l"(p0b) : "r"(hd_base + 16u * (i + 1)));
                    } else {
                        asm volatile("ld.shared.v2.u64 {%0, %1}, [%2];"
                                     : "=l"(p1a), "=l"(p1b) : "r"(hd_base + 16u * (i + 1)));
                    }
                }
                if (i & 1) { fma2(acc0, w[2 * i], p1a); fma2(acc1, w[2 * i + 1], p1b); }
                else       { fma2(acc0, w[2 * i], p0a); fma2(acc1, w[2 * i + 1], p0b); }
            }
            float2 p0 = upk(acc0), p1 = upk(acc1);
            float s = (p0.x + p0.y) + (p1.x + p1.y);
            float tot = s + __shfl_xor_sync(0xffffffffu, s, 1);
            if (half == 0) s_gates[row] = tot;
        } else {
            // ---- scalar warp: x_h = reg_w . h_decayed + reg_b; x_c; loss; imputation ----
            float r0 = reg_w[lane];
            float r1 = (lane + 32 < H) ? reg_w[lane + 32] : 0.0f;
            float r2 = (lane + 64 < H) ? reg_w[lane + 64] : 0.0f;
            float r3 = (lane + 96 < H) ? reg_w[lane + 96] : 0.0f;
            float p = r0 * s_hd[lane] + r1 * s_hd[lane + 32]
                    + r2 * s_hd[lane + 64] + r3 * s_hd[lane + 96];
            #pragma unroll
            for (int o = 16; o > 0; o >>= 1) p += __shfl_xor_sync(0xffffffffu, p, o);
            if (lane == 0) {
                float xv = values[idx], m = masks[idx];
                float x_h = p + reg_b[0];
                float x_c = m * xv + (1.0f - m) * x_h;
                float term = fabsf(xv - x_h) * m / (m + 1e-5f);
                float y = term - lcomp;
                float ts = loss + y;
                lcomp = (ts - loss) - y;
                loss = ts;
                g_imp[dir][idx] = x_c;     // backward dir: reversed output position == idx
                s_scalar[0] = x_c;
                s_scalar[1] = m;
            }
        }
        __syncthreads();

        // ---- pointwise LSTM cell (threads 0..107 own element j) ----
        if (tid < H) {
            const int j = tid;
            float xc = s_scalar[0], m = s_scalar[1];
            float gi = fmaf(s_par[0][j], xc, fmaf(s_par[4][j], m, s_gates[j]          + s_par[8][j]));
            float gf = fmaf(s_par[1][j], xc, fmaf(s_par[5][j], m, s_gates[H + j]      + s_par[9][j]));
            float gg = fmaf(s_par[2][j], xc, fmaf(s_par[6][j], m, s_gates[2 * H + j]  + s_par[10][j]));
            float go = fmaf(s_par[3][j], xc, fmaf(s_par[7][j], m, s_gates[3 * H + j]  + s_par[11][j]));
            float si = sigmoid_fast(gi);
            float sf = sigmoid_fast(gf);
            float so = sigmoid_fast(go);
            float tg = tanh_fast(gg);
            float c  = sf * s_c[j] + si * tg;
            s_c[j] = c;
            float hh = so * tanh_fast(c);
            // fold next step's temporal decay into the h store
            float gam = __expf(-fmaxf(fmaf(dn, s_tdw[j], s_tdb[j]), 0.0f));
            s_hd[j] = hh * gam;
        }
        __syncthreads();
    }

    if (tid == NGATE) g_loss[dir] = loss;
}

// ---------------- combine: imputations + per-block |imp_f - imp_b| partial sums ----------------
__global__ void combine_kernel(float* __restrict__ out)
{
    __shared__ float red[256];
    const int i = blockIdx.x * 256 + threadIdx.x;
    float a = g_imp[0][i];
    float b = g_imp[1][i];
    out[1 + i] = 0.5f * (a + b);
    red[threadIdx.x] = fabsf(a - b);
    __syncthreads();
    #pragma unroll
    for (int s = 128; s > 0; s >>= 1) {
        if (threadIdx.x < s) red[threadIdx.x] += red[threadIdx.x + s];
        __syncthreads();
    }
    if (threadIdx.x == 0) g_part[blockIdx.x] = red[0];
}

__global__ void finalize_kernel(float* __restrict__ out)
{
    __shared__ float red[256];
    red[threadIdx.x] = g_part[threadIdx.x];
    __syncthreads();
    #pragma unroll
    for (int s = 128; s > 0; s >>= 1) {
        if (threadIdx.x < s) red[threadIdx.x] += red[threadIdx.x + s];
        __syncthreads();
    }
    if (threadIdx.x == 0) {
        float loss_c = red[0] / (float)T_LEN;
        out[0] = 0.3f * (g_loss[0] + g_loss[1]) + loss_c;
    }
}

// ---------------- launch ----------------
extern "C" void kernel_launch(void* const* d_in, const int* in_sizes, int n_in,
                              void* d_out, int out_size)
{
    (void)in_sizes; (void)n_in; (void)out_size;
    const float* values   = (const float*)d_in[0];
    const float* masks    = (const float*)d_in[1];
    const float* deltas_f = (const float*)d_in[2];
    const float* deltas_b = (const float*)d_in[3];
    const float* f_td_w   = (const float*)d_in[4];
    const float* f_td_b   = (const float*)d_in[5];
    const float* f_reg_w  = (const float*)d_in[6];
    const float* f_reg_b  = (const float*)d_in[7];
    const float* f_W_ih   = (const float*)d_in[8];
    const float* f_W_hh   = (const float*)d_in[9];
    const float* f_b_ih   = (const float*)d_in[10];
    const float* f_b_hh   = (const float*)d_in[11];
    const float* b_td_w   = (const float*)d_in[12];
    const float* b_td_b   = (const float*)d_in[13];
    const float* b_reg_w  = (const float*)d_in[14];
    const float* b_reg_b  = (const float*)d_in[15];
    const float* b_W_ih   = (const float*)d_in[16];
    const float* b_W_hh   = (const float*)d_in[17];
    const float* b_b_ih   = (const float*)d_in[18];
    const float* b_b_hh   = (const float*)d_in[19];
    float* out = (float*)d_out;

    brits_kernel<<<2, NTHR>>>(values, masks, deltas_f, deltas_b,
                              f_td_w, f_td_b, f_reg_w, f_reg_b, f_W_ih, f_W_hh, f_b_ih, f_b_hh,
                              b_td_w, b_td_b, b_reg_w, b_reg_b, b_W_ih, b_W_hh, b_b_ih, b_b_hh);
    combine_kernel<<<T_LEN / 256, 256>>>(out);
    finalize_kernel<<<1, 256>>>(out);
}

// round 17
// speedup vs baseline: 1.4120x; 1.4120x over previous
#include <cuda_runtime.h>
#include <cstdint>

#define T_LEN 65536
#define H 108
#define G4 432          // 4*H gate rows
#define NGATE 864       // 432 rows x 2 half-row threads (27 warps)
#define NTHR 896        // + 1 scalar warp

// ---------------- device scratch (static: no allocation allowed) ----------------
__device__ float g_imp[2][T_LEN];   // per-direction imputations (forward time order)
__device__ float g_loss[2];
__device__ float g_part[256];

// ---------------- f32x2 packed-FMA helpers ----------------
__device__ __forceinline__ void fma2(unsigned long long &acc, unsigned long long a, unsigned long long b) {
    asm volatile("fma.rn.f32x2 %0, %1, %2, %0;" : "+l"(acc) : "l"(a), "l"(b));
}
__device__ __forceinline__ unsigned long long pk2(float a, float b) {
    unsigned long long r;
    asm("mov.b64 %0, {%1, %2};" : "=l"(r) : "f"(a), "f"(b));
    return r;
}
__device__ __forceinline__ float2 upk(unsigned long long v) {
    float2 r;
    asm("mov.b64 {%0, %1}, %2;" : "=f"(r.x), "=f"(r.y) : "l"(v));
    return r;
}

// HW tanh (MUFU.TANH): 1 op instead of EX2+RCP chains
__device__ __forceinline__ float tanh_fast(float x) {
    float y;
    asm("tanh.approx.f32 %0, %1;" : "=f"(y) : "f"(x));
    return y;
}
__device__ __forceinline__ float sigmoid_fast(float x) {
    return fmaf(tanh_fast(0.5f * x), 0.5f, 0.5f);
}

// ---------------- main recurrence: one block per direction ----------------
__global__ void __launch_bounds__(NTHR, 1) brits_kernel(
    const float* __restrict__ values,  const float* __restrict__ masks,
    const float* __restrict__ deltas_f, const float* __restrict__ deltas_b,
    const float* __restrict__ f_td_w,  const float* __restrict__ f_td_b,
    const float* __restrict__ f_reg_w, const float* __restrict__ f_reg_b,
    const float* __restrict__ f_W_ih,  const float* __restrict__ f_W_hh,
    const float* __restrict__ f_b_ih,  const float* __restrict__ f_b_hh,
    const float* __restrict__ b_td_w,  const float* __restrict__ b_td_b,
    const float* __restrict__ b_reg_w, const float* __restrict__ b_reg_b,
    const float* __restrict__ b_W_ih,  const float* __restrict__ b_W_hh,
    const float* __restrict__ b_b_ih,  const float* __restrict__ b_b_hh)
{
    const int dir = blockIdx.x;
    const float* td_w  = dir ? b_td_w  : f_td_w;
    const float* td_b  = dir ? b_td_b  : f_td_b;
    const float* reg_w = dir ? b_reg_w : f_reg_w;
    const float* reg_b = dir ? b_reg_b : f_reg_b;
    const float* W_ih  = dir ? b_W_ih  : f_W_ih;
    const float* W_hh  = dir ? b_W_hh  : f_W_hh;
    const float* b_ih  = dir ? b_b_ih  : f_b_ih;
    const float* b_hh  = dir ? b_b_hh  : f_b_hh;
    const float* deltas = dir ? deltas_b : deltas_f;

    __shared__ __align__(16) float s_hd[128];   // decayed hidden; [108..127] = 0 pad
    __shared__ float s_gates[G4];               // W_hh @ h_decayed per gate row
    __shared__ float s_scalar[2];               // {x_c, m} for current step
    __shared__ float s_par[12][H];              // input weights / fused biases, SoA
    __shared__ float s_c[H];                    // cell state (smem to spare regs)
    __shared__ float s_tdw[H], s_tdb[H];        // decay params (smem)

    const int tid  = threadIdx.x;
    const int lane = tid & 31;
    const int row  = tid >> 1;     // gate row (gate threads)
    const int half = tid & 1;      // K-half: 0 -> floats [0,56), 1 -> [56,112)

    // ---- one-time init: half-row of W_hh in registers, 28 x f32x2 ----
    unsigned long long w[28];
    if (tid < NGATE) {
        const float* rw = W_hh + row * H + half * 56;
        const int nreal = half ? 52 : 56;     // valid floats in this half
        #pragma unroll
        for (int i = 0; i < 28; i++) {
            float a = (2 * i     < nreal) ? rw[2 * i]     : 0.0f;
            float b = (2 * i + 1 < nreal) ? rw[2 * i + 1] : 0.0f;
            w[i] = pk2(a, b);
        }
    } else {
        #pragma unroll
        for (int i = 0; i < 28; i++) w[i] = 0ull;
    }

    // s_par[kind*4+q][j]: kind0=W_ih[:,0], kind1=W_ih[:,1], kind2=b_ih+b_hh; row r=q*H+j
    for (int k = tid; k < 12 * H; k += NTHR) {
        int j = k % H;
        int f = k / H;
        int q = f & 3;
        int kind = f >> 2;
        int r = q * H + j;
        float v;
        if (kind == 0)      v = W_ih[2 * r];
        else if (kind == 1) v = W_ih[2 * r + 1];
        else                v = b_ih[r] + b_hh[r];
        s_par[f][j] = v;
    }

    if (tid < H) {
        s_c[tid]   = 0.0f;
        s_tdw[tid] = td_w[tid];
        s_tdb[tid] = td_b[tid];
    }
    if (tid < 128) s_hd[tid] = 0.0f;

    float loss = 0.0f, lcomp = 0.0f;   // Kahan loss accumulator (scalar warp lane 0)
    __syncthreads();

    const uint32_t hd_base = (uint32_t)__cvta_generic_to_shared(s_hd) + (uint32_t)(half * 224);

    for (int t = 0; t < T_LEN; ++t) {
        const int idx = dir ? (T_LEN - 1 - t) : t;

        // prefetch next step's delta early (LDG hides behind the matvec)
        float dn = 0.0f;
        if (tid < H) {
            int tn = (t + 1 < T_LEN) ? (t + 1) : (T_LEN - 1);
            dn = deltas[tn];
        }

        if (tid < NGATE) {
            // ---- half-row matvec: 14 x LDS.128 feeding 28 x fma2 (2 chains) ----
            unsigned long long acc0 = 0ull, acc1 = 0ull;
            #pragma unroll
            for (int i = 0; i < 14; i++) {
                unsigned long long h0, h1;
                asm volatile("ld.shared.v2.u64 {%0, %1}, [%2];"
                             : "=l"(h0), "=l"(h1) : "r"(hd_base + 16u * i));
                fma2(acc0, w[2 * i],     h0);
                fma2(acc1, w[2 * i + 1], h1);
            }
            float2 p0 = upk(acc0), p1 = upk(acc1);
            float s = (p0.x + p0.y) + (p1.x + p1.y);
            float tot = s + __shfl_xor_sync(0xffffffffu, s, 1);
            if (half == 0) s_gates[row] = tot;
        } else {
            // ---- scalar warp: x_h = reg_w . h_decayed + reg_b; x_c; loss; imputation ----
            float r0 = reg_w[lane];
            float r1 = (lane + 32 < H) ? reg_w[lane + 32] : 0.0f;
            float r2 = (lane + 64 < H) ? reg_w[lane + 64] : 0.0f;
            float r3 = (lane + 96 < H) ? reg_w[lane + 96] : 0.0f;
            float p = r0 * s_hd[lane] + r1 * s_hd[lane + 32]
                    + r2 * s_hd[lane + 64] + r3 * s_hd[lane + 96];
            #pragma unroll
            for (int o = 16; o > 0; o >>= 1) p += __shfl_xor_sync(0xffffffffu, p, o);
            if (lane == 0) {
                float xv = values[idx], m = masks[idx];
                float x_h = p + reg_b[0];
                float x_c = m * xv + (1.0f - m) * x_h;
                float term = fabsf(xv - x_h) * m / (m + 1e-5f);
                float y = term - lcomp;
                float ts = loss + y;
                lcomp = (ts - loss) - y;
                loss = ts;
                g_imp[dir][idx] = x_c;     // backward dir: reversed output position == idx
                s_scalar[0] = x_c;
                s_scalar[1] = m;
            }
        }
        __syncthreads();

        // ---- pointwise LSTM cell (threads 0..107 own element j) ----
        if (tid < H) {
            const int j = tid;
            float xc = s_scalar[0], m = s_scalar[1];
            float gi = fmaf(s_par[0][j], xc, fmaf(s_par[4][j], m, s_gates[j]          + s_par[8][j]));
            float gf = fmaf(s_par[1][j], xc, fmaf(s_par[5][j], m, s_gates[H + j]      + s_par[9][j]));
            float gg = fmaf(s_par[2][j], xc, fmaf(s_par[6][j], m, s_gates[2 * H + j]  + s_par[10][j]));
            float go = fmaf(s_par[3][j], xc, fmaf(s_par[7][j], m, s_gates[3 * H + j]  + s_par[11][j]));
            float si = sigmoid_fast(gi);
            float sf = sigmoid_fast(gf);
            float so = sigmoid_fast(go);
            float tg = tanh_fast(gg);
            float c  = sf * s_c[j] + si * tg;
            s_c[j] = c;
            float hh = so * tanh_fast(c);
            // fold next step's temporal decay into the h store
            float gam = __expf(-fmaxf(fmaf(dn, s_tdw[j], s_tdb[j]), 0.0f));
            s_hd[j] = hh * gam;
        }
        __syncthreads();
    }

    if (tid == NGATE) g_loss[dir] = loss;
}

// ---------------- combine: imputations + per-block |imp_f - imp_b| partial sums ----------------
__global__ void combine_kernel(float* __restrict__ out)
{
    __shared__ float red[256];
    const int i = blockIdx.x * 256 + threadIdx.x;
    float a = g_imp[0][i];
    float b = g_imp[1][i];
    out[1 + i] = 0.5f * (a + b);
    red[threadIdx.x] = fabsf(a - b);
    __syncthreads();
    #pragma unroll
    for (int s = 128; s > 0; s >>= 1) {
        if (threadIdx.x < s) red[threadIdx.x] += red[threadIdx.x + s];
        __syncthreads();
    }
    if (threadIdx.x == 0) g_part[blockIdx.x] = red[0];
}

__global__ void finalize_kernel(float* __restrict__ out)
{
    __shared__ float red[256];
    red[threadIdx.x] = g_part[threadIdx.x];
    __syncthreads();
    #pragma unroll
    for (int s = 128; s > 0; s >>= 1) {
        if (threadIdx.x < s) red[threadIdx.x] += red[threadIdx.x + s];
        __syncthreads();
    }
    if (threadIdx.x == 0) {
        float loss_c = red[0] / (float)T_LEN;
        out[0] = 0.3f * (g_loss[0] + g_loss[1]) + loss_c;
    }
}

// ---------------- launch ----------------
extern "C" void kernel_launch(void* const* d_in, const int* in_sizes, int n_in,
                              void* d_out, int out_size)
{
    (void)in_sizes; (void)n_in; (void)out_size;
    const float* values   = (const float*)d_in[0];
    const float* masks    = (const float*)d_in[1];
    const float* deltas_f = (const float*)d_in[2];
    const float* deltas_b = (const float*)d_in[3];
    const float* f_td_w   = (const float*)d_in[4];
    const float* f_td_b   = (const float*)d_in[5];
    const float* f_reg_w  = (const float*)d_in[6];
    const float* f_reg_b  = (const float*)d_in[7];
    const float* f_W_ih   = (const float*)d_in[8];
    const float* f_W_hh   = (const float*)d_in[9];
    const float* f_b_ih   = (const float*)d_in[10];
    const float* f_b_hh   = (const float*)d_in[11];
    const float* b_td_w   = (const float*)d_in[12];
    const float* b_td_b   = (const float*)d_in[13];
    const float* b_reg_w  = (const float*)d_in[14];
    const float* b_reg_b  = (const float*)d_in[15];
    const float* b_W_ih   = (const float*)d_in[16];
    const float* b_W_hh   = (const float*)d_in[17];
    const float* b_b_ih   = (const float*)d_in[18];
    const float* b_b_hh   = (const float*)d_in[19];
    float* out = (float*)d_out;

    brits_kernel<<<2, NTHR>>>(values, masks, deltas_f, deltas_b,
                              f_td_w, f_td_b, f_reg_w, f_reg_b, f_W_ih, f_W_hh, f_b_ih, f_b_hh,
                              b_td_w, b_td_b, b_reg_w, b_reg_b, b_W_ih, b_W_hh, b_b_ih, b_b_hh);
    combine_kernel<<<T_LEN / 256, 256>>>(out);
    finalize_kernel<<<1, 256>>>(out);
}